// round 14
// baseline (speedup 1.0000x reference)
#include <cuda_runtime.h>
#include <cuda_fp16.h>

// 2-layer GCN. ELL adjacency (cap 128). R14: one-line-per-LDG gathers —
// each edge read by a full-warp LDG.32 (lanes 0-15 = 16 channels, 16-31
// duplicates) so every LDG touches exactly ONE 128B line -> L1tex runs at the
// 1.0 cyc/wf cross-LDG rate instead of 2.07 within-LDG replay. Lane = channel:
// no reduction tree, no predication (warp-uniform loop bounds).
#define NN 100000
#define NE 3200000
#define C0 13
#define C0P 16
#define C1 32
#define C2 16
#define CAP 128
#define NPW 4   // nodes per warp in gather kernels

__device__ int    g_cur[NN];
__device__ int    g_ell[NN * CAP];   // static zero-init
__device__ float  g_dinv[NN];
__device__ __align__(16) float g_g0[NN * C0P];   // x * dinv, 64B rows
__device__ __align__(16) float g_agg[NN * C0P];  // dinv * (sum + self)
__device__ __align__(16) float g_g2[NN * C2];    // (h W2) * dinv, 64B rows
__device__ int    g_odd_nonzero;

// ---------------- init: zero counters + detect int64 vs int32 ----------------
__global__ void k_init(const unsigned* __restrict__ p, int n, int E) {
    int i = blockIdx.x * blockDim.x + threadIdx.x;
    if (i < n) g_cur[i] = 0;
    if (blockIdx.x == 0) {
        if (threadIdx.x == 0) g_odd_nonzero = 0;
        __syncthreads();
        int pairs = E < 2048 ? E : 2048;
        int any = 0;
        for (int j = threadIdx.x; j < pairs; j += blockDim.x)
            if (p[2 * j + 1] != 0u) any = 1;
        if (any) atomicOr(&g_odd_nonzero, 1);
    }
}

// ---------------- build ELL + degree: 2 edges/thread, 16B index loads ----------------
__global__ void k_fill(const void* __restrict__ p, int E) {
    int i = blockIdx.x * blockDim.x + threadIdx.x;   // handles edges 2i, 2i+1
    int e0 = 2 * i;
    if (e0 >= E) return;
    int has2 = (e0 + 1 < E);
    int s0, s1, d0, d1;
    if (g_odd_nonzero == 0) {                        // int64 input
        const long long* q = (const long long*)p;
        longlong2 ts = ((const longlong2*)q)[i];
        longlong2 td = *(const longlong2*)(q + E + e0);
        s0 = (int)ts.x; s1 = (int)ts.y;
        d0 = (int)td.x; d1 = (int)td.y;
    } else {                                          // int32 input
        const int* q = (const int*)p;
        int2 ts = ((const int2*)q)[i];
        int2 td = *(const int2*)(q + E + e0);
        s0 = ts.x; s1 = ts.y;
        d0 = td.x; d1 = td.y;
    }
    int pos0 = atomicAdd(&g_cur[d0], 1);
    if (pos0 < CAP) g_ell[d0 * CAP + pos0] = s0;
    if (has2) {
        int pos1 = atomicAdd(&g_cur[d1], 1);
        if (pos1 < CAP) g_ell[d1 * CAP + pos1] = s1;
    }
}

// ---------------- scale0: g0 = pad16(x) * dinv; also store dinv ----------------
__global__ void k_scale0(const float* __restrict__ x, int n) {
    int t = blockIdx.x * blockDim.x + threadIdx.x;   // 4 threads per node
    int node = t >> 2, co = t & 3;
    if (node >= n) return;
    float di = rsqrtf((float)(g_cur[node] + 1));
    if (co == 0) g_dinv[node] = di;
    float4 v;
    const float* xr = x + node * C0;
    int c = 4 * co;
    v.x = (c     < C0) ? xr[c]     * di : 0.0f;
    v.y = (c + 1 < C0) ? xr[c + 1] * di : 0.0f;
    v.z = (c + 2 < C0) ? xr[c + 2] * di : 0.0f;
    v.w = (c + 3 < C0) ? xr[c + 3] * di : 0.0f;
    ((float4*)g_g0)[node * 4 + co] = v;
}

// ---------------- gather1: agg[node] = dinv * (sum_in g0[src] + g0[node]) ----------------
// Lane L accumulates channel L&15; one full-warp LDG per edge = one 128B line.
__global__ void __launch_bounds__(256, 8)
k_gather1(int n) {
    int warp = threadIdx.x >> 5, lane = threadIdx.x & 31;
    int ch = lane & 15;
    const float* __restrict__ g0 = g_g0;

    int node0 = (blockIdx.x * 8 + warp) * NPW;
    int node1 = node0 + NPW; if (node1 > n) node1 = n;
    for (int node = node0; node < node1; node++) {
        int deg = g_cur[node]; if (deg > CAP) deg = CAP;
        float acc = __ldg(&g0[node * C0P + ch]);     // self loop
        const int* __restrict__ row = &g_ell[node * CAP];
        for (int j0 = 0; j0 < deg; j0 += 32) {
            int idx = row[j0 + lane];                // in-bounds; junk lanes unused
            int m = deg - j0; if (m > 32) m = 32;    // warp-uniform bound
            #pragma unroll 4
            for (int k = 0; k < m; k++) {
                int b = __shfl_sync(~0u, idx, k);
                acc += __ldg(&g0[b * C0P + ch]);
            }
        }
        if (lane < 16) g_agg[node * C0P + lane] = acc * g_dinv[node];
    }
}

// ---------------- mlp: g2[node] = dinv * (relu(agg W1 + b1) W2), thread/node ----------------
__global__ void k_mlp(const float* __restrict__ W1, const float* __restrict__ b1,
                      const float* __restrict__ W2, int n) {
    __shared__ __align__(16) float sW1T[C1 * C0P];   // [c][k], k padded to 16, zeros
    __shared__ __align__(16) float sW2[C1 * C2];     // [c][j]
    __shared__ float sb1[C1];
    for (int i = threadIdx.x; i < C1 * C0P; i += blockDim.x) {
        int c = i >> 4, k = i & 15;
        sW1T[i] = (k < C0) ? W1[k * C1 + c] : 0.0f;
    }
    for (int i = threadIdx.x; i < C1 * C2; i += blockDim.x) sW2[i] = W2[i];
    if (threadIdx.x < C1) sb1[threadIdx.x] = b1[threadIdx.x];
    __syncthreads();
    int node = blockIdx.x * blockDim.x + threadIdx.x;
    if (node >= n) return;
    const float4* av = &((const float4*)g_agg)[node * 4];
    float4 A0 = av[0], A1 = av[1], A2 = av[2], A3 = av[3];
    float di = g_dinv[node];
    float o[C2];
    #pragma unroll
    for (int j = 0; j < C2; j++) o[j] = 0.0f;
    #pragma unroll
    for (int c = 0; c < C1; c++) {
        const float4* wt = (const float4*)&sW1T[c * C0P];
        float4 w0 = wt[0], w1 = wt[1], w2 = wt[2], w3 = wt[3];
        float h = sb1[c];
        h = fmaf(A0.x, w0.x, h); h = fmaf(A0.y, w0.y, h);
        h = fmaf(A0.z, w0.z, h); h = fmaf(A0.w, w0.w, h);
        h = fmaf(A1.x, w1.x, h); h = fmaf(A1.y, w1.y, h);
        h = fmaf(A1.z, w1.z, h); h = fmaf(A1.w, w1.w, h);
        h = fmaf(A2.x, w2.x, h); h = fmaf(A2.y, w2.y, h);
        h = fmaf(A2.z, w2.z, h); h = fmaf(A2.w, w2.w, h);
        h = fmaf(A3.x, w3.x, h);
        h = fmaxf(h, 0.0f);
        const float4* wu = (const float4*)&sW2[c * C2];
        float4 u0 = wu[0], u1 = wu[1], u2 = wu[2], u3 = wu[3];
        o[0]  = fmaf(h, u0.x, o[0]);  o[1]  = fmaf(h, u0.y, o[1]);
        o[2]  = fmaf(h, u0.z, o[2]);  o[3]  = fmaf(h, u0.w, o[3]);
        o[4]  = fmaf(h, u1.x, o[4]);  o[5]  = fmaf(h, u1.y, o[5]);
        o[6]  = fmaf(h, u1.z, o[6]);  o[7]  = fmaf(h, u1.w, o[7]);
        o[8]  = fmaf(h, u2.x, o[8]);  o[9]  = fmaf(h, u2.y, o[9]);
        o[10] = fmaf(h, u2.z, o[10]); o[11] = fmaf(h, u2.w, o[11]);
        o[12] = fmaf(h, u3.x, o[12]); o[13] = fmaf(h, u3.y, o[13]);
        o[14] = fmaf(h, u3.z, o[14]); o[15] = fmaf(h, u3.w, o[15]);
    }
    float4* ov = &((float4*)g_g2)[node * 4];
    #pragma unroll
    for (int q = 0; q < 4; q++) {
        float4 r;
        r.x = o[4 * q + 0] * di; r.y = o[4 * q + 1] * di;
        r.z = o[4 * q + 2] * di; r.w = o[4 * q + 3] * di;
        ov[q] = r;
    }
}

// ---------------- layer2: out[node] = dinv * (sum g2[src] + g2[node]) + b2 ----------------
__global__ void __launch_bounds__(256, 8)
k_layer2(float* __restrict__ out, const float* __restrict__ b2, int n) {
    int warp = threadIdx.x >> 5, lane = threadIdx.x & 31;
    int ch = lane & 15;
    const float* __restrict__ g2 = g_g2;
    float bb = __ldg(&b2[ch]);                       // hoisted bias

    int node0 = (blockIdx.x * 8 + warp) * NPW;
    int node1 = node0 + NPW; if (node1 > n) node1 = n;
    for (int node = node0; node < node1; node++) {
        int deg = g_cur[node]; if (deg > CAP) deg = CAP;
        float acc = __ldg(&g2[node * C2 + ch]);      // self loop
        const int* __restrict__ row = &g_ell[node * CAP];
        for (int j0 = 0; j0 < deg; j0 += 32) {
            int idx = row[j0 + lane];
            int m = deg - j0; if (m > 32) m = 32;
            #pragma unroll 4
            for (int k = 0; k < m; k++) {
                int b = __shfl_sync(~0u, idx, k);
                acc += __ldg(&g2[b * C2 + ch]);
            }
        }
        if (lane < 16) out[node * C2 + lane] = fmaf(g_dinv[node], acc, bb);
    }
}

extern "C" void kernel_launch(void* const* d_in, const int* in_sizes, int n_in,
                              void* d_out, int out_size) {
    const float* x  = (const float*)d_in[0];
    const void*  ei = d_in[1];
    const float* W1 = (const float*)d_in[2];
    const float* b1 = (const float*)d_in[3];
    const float* W2 = (const float*)d_in[4];
    const float* b2 = (const float*)d_in[5];
    float* out = (float*)d_out;

    int n = in_sizes[0] / C0; if (n > NN) n = NN;
    int E = in_sizes[1] / 2;  if (E > NE) E = NE;
    int nwarps = (n + NPW - 1) / NPW;
    int nblocks = (nwarps + 7) / 8;
    int npairs = (E + 1) / 2;

    k_init<<<(n + 255) / 256, 256>>>((const unsigned*)ei, n, E);
    k_fill<<<(npairs + 255) / 256, 256>>>(ei, E);
    k_scale0<<<(4 * n + 255) / 256, 256>>>(x, n);
    k_gather1<<<nblocks, 256>>>(n);
    k_mlp<<<(n + 255) / 256, 256>>>(W1, b1, W2, n);
    k_layer2<<<nblocks, 256>>>(out, b2, n);
}

// round 15
// speedup vs baseline: 1.4769x; 1.4769x over previous
#include <cuda_runtime.h>
#include <cuda_fp16.h>

// 2-layer GCN. ELL adjacency (cap 128). R15 = R13 structure (best: 111.4us)
// + PAIRED-NODE gather kernels: two nodes in flight per warp with independent
// accumulators, interleaved LDG/SHFL streams -> 2x ILP on the per-node chain.
#define NN 100000
#define NE 3200000
#define C0 13
#define C0P 16
#define C1 32
#define C2 16
#define CAP 128
#define NPW 4   // nodes per warp (processed as 2 pairs)

#define ADDX2(a, b) asm("add.rn.f32x2 %0, %1, %2;" : "=l"(a) : "l"(a), "l"(b))

__device__ int    g_cur[NN];
__device__ int    g_ell[NN * CAP];   // static zero-init
__device__ float  g_dinv[NN];
__device__ __align__(16) float g_g0[NN * C0P];   // x * dinv, 64B rows
__device__ __align__(16) float g_agg[NN * C0P];  // dinv * (sum + self)
__device__ __align__(16) float g_g2[NN * C2];    // (h W2) * dinv, 64B rows
__device__ int    g_odd_nonzero;

// ---------------- init: zero counters + detect int64 vs int32 ----------------
__global__ void k_init(const unsigned* __restrict__ p, int n, int E) {
    int i = blockIdx.x * blockDim.x + threadIdx.x;
    if (i < n) g_cur[i] = 0;
    if (blockIdx.x == 0) {
        if (threadIdx.x == 0) g_odd_nonzero = 0;
        __syncthreads();
        int pairs = E < 2048 ? E : 2048;
        int any = 0;
        for (int j = threadIdx.x; j < pairs; j += blockDim.x)
            if (p[2 * j + 1] != 0u) any = 1;
        if (any) atomicOr(&g_odd_nonzero, 1);
    }
}

// ---------------- build ELL + degree: 2 edges/thread, 16B index loads ----------------
__global__ void k_fill(const void* __restrict__ p, int E) {
    int i = blockIdx.x * blockDim.x + threadIdx.x;
    int e0 = 2 * i;
    if (e0 >= E) return;
    int has2 = (e0 + 1 < E);
    int s0, s1, d0, d1;
    if (g_odd_nonzero == 0) {
        const long long* q = (const long long*)p;
        longlong2 ts = ((const longlong2*)q)[i];
        longlong2 td = *(const longlong2*)(q + E + e0);
        s0 = (int)ts.x; s1 = (int)ts.y;
        d0 = (int)td.x; d1 = (int)td.y;
    } else {
        const int* q = (const int*)p;
        int2 ts = ((const int2*)q)[i];
        int2 td = *(const int2*)(q + E + e0);
        s0 = ts.x; s1 = ts.y;
        d0 = td.x; d1 = td.y;
    }
    int pos0 = atomicAdd(&g_cur[d0], 1);
    if (pos0 < CAP) g_ell[d0 * CAP + pos0] = s0;
    if (has2) {
        int pos1 = atomicAdd(&g_cur[d1], 1);
        if (pos1 < CAP) g_ell[d1 * CAP + pos1] = s1;
    }
}

// ---------------- scale0: g0 = pad16(x) * dinv; also store dinv ----------------
__global__ void k_scale0(const float* __restrict__ x, int n) {
    int t = blockIdx.x * blockDim.x + threadIdx.x;   // 4 threads per node
    int node = t >> 2, co = t & 3;
    if (node >= n) return;
    float di = rsqrtf((float)(g_cur[node] + 1));
    if (co == 0) g_dinv[node] = di;
    float4 v;
    const float* xr = x + node * C0;
    int c = 4 * co;
    v.x = (c     < C0) ? xr[c]     * di : 0.0f;
    v.y = (c + 1 < C0) ? xr[c + 1] * di : 0.0f;
    v.z = (c + 2 < C0) ? xr[c + 2] * di : 0.0f;
    v.w = (c + 3 < C0) ? xr[c + 3] * di : 0.0f;
    ((float4*)g_g0)[node * 4 + co] = v;
}

// ---------------- paired gather core (shared shape for both layers) ----------------
// vsrc rows: 4 x ulonglong2 (64B) per node. Writes via functor-free epilogues below.
__device__ __forceinline__ void gather_pair(
    const ulonglong2* __restrict__ vsrc, int nodeA, int nodeB, int hasB,
    int lane, int grp, int co,
    unsigned long long& aA0, unsigned long long& aA1,
    unsigned long long& aB0, unsigned long long& aB1)
{
    int degA = g_cur[nodeA]; if (degA > CAP) degA = CAP;
    int degB = 0;
    if (hasB) { degB = g_cur[nodeB]; if (degB > CAP) degB = CAP; }
    int idxA = g_ell[nodeA * CAP + lane];
    int idxB = hasB ? g_ell[nodeB * CAP + lane] : 0;
    aA0 = aA1 = aB0 = aB1 = 0ULL;
    if (grp == 0) {                       // self loops
        ulonglong2 t = vsrc[nodeA * 4 + co];
        aA0 = t.x; aA1 = t.y;
        if (hasB) {
            ulonglong2 u = vsrc[nodeB * 4 + co];
            aB0 = u.x; aB1 = u.y;
        }
    }
    for (int j0 = 0; j0 < degA || j0 < degB; j0 += 32) {
        if (j0 > 0) {                     // reload indices for later chunks
            if (j0 < degA) idxA = g_ell[nodeA * CAP + j0 + lane];
            if (j0 < degB) idxB = g_ell[nodeB * CAP + j0 + lane];
        }
        int mA = degA - j0; mA = mA < 0 ? 0 : (mA > 32 ? 32 : mA);
        int mB = degB - j0; mB = mB < 0 ? 0 : (mB > 32 ? 32 : mB);
        if (mA == 32 && mB == 32) {
            #pragma unroll
            for (int k = 0; k < 4; k++) {
                int bA = __shfl_sync(~0u, idxA, 8 * k + grp) * 4;
                int bB = __shfl_sync(~0u, idxB, 8 * k + grp) * 4;
                ulonglong2 tA = vsrc[bA + co];
                ulonglong2 tB = vsrc[bB + co];
                ADDX2(aA0, tA.x); ADDX2(aA1, tA.y);
                ADDX2(aB0, tB.x); ADDX2(aB1, tB.y);
            }
        } else {
            int kA = (mA + 7) >> 3, kB = (mB + 7) >> 3;
            int kmax = kA > kB ? kA : kB;     // warp-uniform
            for (int k = 0; k < kmax; k++) {
                int kk = 8 * k + grp;
                int bA = __shfl_sync(~0u, idxA, kk < mA ? kk : 0) * 4;
                int bB = __shfl_sync(~0u, idxB, kk < mB ? kk : 0) * 4;
                if (kk < mA) {
                    ulonglong2 tA = vsrc[bA + co];
                    ADDX2(aA0, tA.x); ADDX2(aA1, tA.y);
                }
                if (kk < mB) {
                    ulonglong2 tB = vsrc[bB + co];
                    ADDX2(aB0, tB.x); ADDX2(aB1, tB.y);
                }
            }
        }
    }
}

__device__ __forceinline__ void reduce8(
    unsigned long long a0, unsigned long long a1,
    float& f0, float& f1, float& f2, float& f3)
{
    asm("mov.b64 {%0,%1}, %2;" : "=f"(f0), "=f"(f1) : "l"(a0));
    asm("mov.b64 {%0,%1}, %2;" : "=f"(f2), "=f"(f3) : "l"(a1));
    #pragma unroll
    for (int o = 4; o <= 16; o <<= 1) {
        f0 += __shfl_xor_sync(~0u, f0, o);
        f1 += __shfl_xor_sync(~0u, f1, o);
        f2 += __shfl_xor_sync(~0u, f2, o);
        f3 += __shfl_xor_sync(~0u, f3, o);
    }
}

// ---------------- gather1: agg[node] = dinv * (sum_in g0[src] + g0[node]) ----------------
__global__ void __launch_bounds__(256, 6)
k_gather1(int n) {
    int warp = threadIdx.x >> 5, lane = threadIdx.x & 31;
    int grp = lane >> 2, co = lane & 3;
    const ulonglong2* __restrict__ g0v = (const ulonglong2*)g_g0;

    int node0 = (blockIdx.x * 8 + warp) * NPW;
    int node1 = node0 + NPW; if (node1 > n) node1 = n;
    for (int pn = node0; pn < node1; pn += 2) {
        int nodeA = pn, nodeB = pn + 1;
        int hasB = (nodeB < node1);
        unsigned long long aA0, aA1, aB0, aB1;
        gather_pair(g0v, nodeA, hasB ? nodeB : nodeA, hasB, lane, grp, co,
                    aA0, aA1, aB0, aB1);
        float f0, f1, f2, f3;
        reduce8(aA0, aA1, f0, f1, f2, f3);
        float g0r, g1r, g2r, g3r;
        reduce8(aB0, aB1, g0r, g1r, g2r, g3r);
        if (lane < 4) {
            float di = g_dinv[nodeA];
            float4 a;
            a.x = f0 * di; a.y = f1 * di; a.z = f2 * di; a.w = f3 * di;
            ((float4*)g_agg)[nodeA * 4 + co] = a;
            if (hasB) {
                float dj = g_dinv[nodeB];
                float4 b;
                b.x = g0r * dj; b.y = g1r * dj; b.z = g2r * dj; b.w = g3r * dj;
                ((float4*)g_agg)[nodeB * 4 + co] = b;
            }
        }
    }
}

// ---------------- mlp: g2[node] = dinv * (relu(agg W1 + b1) W2), thread/node ----------------
__global__ void k_mlp(const float* __restrict__ W1, const float* __restrict__ b1,
                      const float* __restrict__ W2, int n) {
    __shared__ __align__(16) float sW1T[C1 * C0P];
    __shared__ __align__(16) float sW2[C1 * C2];
    __shared__ float sb1[C1];
    for (int i = threadIdx.x; i < C1 * C0P; i += blockDim.x) {
        int c = i >> 4, k = i & 15;
        sW1T[i] = (k < C0) ? W1[k * C1 + c] : 0.0f;
    }
    for (int i = threadIdx.x; i < C1 * C2; i += blockDim.x) sW2[i] = W2[i];
    if (threadIdx.x < C1) sb1[threadIdx.x] = b1[threadIdx.x];
    __syncthreads();
    int node = blockIdx.x * blockDim.x + threadIdx.x;
    if (node >= n) return;
    const float4* av = &((const float4*)g_agg)[node * 4];
    float4 A0 = av[0], A1 = av[1], A2 = av[2], A3 = av[3];
    float di = g_dinv[node];
    float o[C2];
    #pragma unroll
    for (int j = 0; j < C2; j++) o[j] = 0.0f;
    #pragma unroll
    for (int c = 0; c < C1; c++) {
        const float4* wt = (const float4*)&sW1T[c * C0P];
        float4 w0 = wt[0], w1 = wt[1], w2 = wt[2], w3 = wt[3];
        float h = sb1[c];
        h = fmaf(A0.x, w0.x, h); h = fmaf(A0.y, w0.y, h);
        h = fmaf(A0.z, w0.z, h); h = fmaf(A0.w, w0.w, h);
        h = fmaf(A1.x, w1.x, h); h = fmaf(A1.y, w1.y, h);
        h = fmaf(A1.z, w1.z, h); h = fmaf(A1.w, w1.w, h);
        h = fmaf(A2.x, w2.x, h); h = fmaf(A2.y, w2.y, h);
        h = fmaf(A2.z, w2.z, h); h = fmaf(A2.w, w2.w, h);
        h = fmaf(A3.x, w3.x, h);
        h = fmaxf(h, 0.0f);
        const float4* wu = (const float4*)&sW2[c * C2];
        float4 u0 = wu[0], u1 = wu[1], u2 = wu[2], u3 = wu[3];
        o[0]  = fmaf(h, u0.x, o[0]);  o[1]  = fmaf(h, u0.y, o[1]);
        o[2]  = fmaf(h, u0.z, o[2]);  o[3]  = fmaf(h, u0.w, o[3]);
        o[4]  = fmaf(h, u1.x, o[4]);  o[5]  = fmaf(h, u1.y, o[5]);
        o[6]  = fmaf(h, u1.z, o[6]);  o[7]  = fmaf(h, u1.w, o[7]);
        o[8]  = fmaf(h, u2.x, o[8]);  o[9]  = fmaf(h, u2.y, o[9]);
        o[10] = fmaf(h, u2.z, o[10]); o[11] = fmaf(h, u2.w, o[11]);
        o[12] = fmaf(h, u3.x, o[12]); o[13] = fmaf(h, u3.y, o[13]);
        o[14] = fmaf(h, u3.z, o[14]); o[15] = fmaf(h, u3.w, o[15]);
    }
    float4* ov = &((float4*)g_g2)[node * 4];
    #pragma unroll
    for (int q = 0; q < 4; q++) {
        float4 r;
        r.x = o[4 * q + 0] * di; r.y = o[4 * q + 1] * di;
        r.z = o[4 * q + 2] * di; r.w = o[4 * q + 3] * di;
        ov[q] = r;
    }
}

// ---------------- layer2: out = dinv * (sum g2[src] + g2[node]) + b2 ----------------
__global__ void __launch_bounds__(256, 6)
k_layer2(float* __restrict__ out, const float* __restrict__ b2, int n) {
    int warp = threadIdx.x >> 5, lane = threadIdx.x & 31;
    int grp = lane >> 2, co = lane & 3;
    const ulonglong2* __restrict__ g2v = (const ulonglong2*)g_g2;

    int node0 = (blockIdx.x * 8 + warp) * NPW;
    int node1 = node0 + NPW; if (node1 > n) node1 = n;
    for (int pn = node0; pn < node1; pn += 2) {
        int nodeA = pn, nodeB = pn + 1;
        int hasB = (nodeB < node1);
        unsigned long long aA0, aA1, aB0, aB1;
        gather_pair(g2v, nodeA, hasB ? nodeB : nodeA, hasB, lane, grp, co,
                    aA0, aA1, aB0, aB1);
        float f0, f1, f2, f3;
        reduce8(aA0, aA1, f0, f1, f2, f3);
        float g0r, g1r, g2r, g3r;
        reduce8(aB0, aB1, g0r, g1r, g2r, g3r);
        if (lane < 4) {
            float4 bb = ((const float4*)b2)[co];
            float di = g_dinv[nodeA];
            float4 a;
            a.x = fmaf(di, f0, bb.x); a.y = fmaf(di, f1, bb.y);
            a.z = fmaf(di, f2, bb.z); a.w = fmaf(di, f3, bb.w);
            ((float4*)out)[nodeA * 4 + co] = a;
            if (hasB) {
                float dj = g_dinv[nodeB];
                float4 b;
                b.x = fmaf(dj, g0r, bb.x); b.y = fmaf(dj, g1r, bb.y);
                b.z = fmaf(dj, g2r, bb.z); b.w = fmaf(dj, g3r, bb.w);
                ((float4*)out)[nodeB * 4 + co] = b;
            }
        }
    }
}

extern "C" void kernel_launch(void* const* d_in, const int* in_sizes, int n_in,
                              void* d_out, int out_size) {
    const float* x  = (const float*)d_in[0];
    const void*  ei = d_in[1];
    const float* W1 = (const float*)d_in[2];
    const float* b1 = (const float*)d_in[3];
    const float* W2 = (const float*)d_in[4];
    const float* b2 = (const float*)d_in[5];
    float* out = (float*)d_out;

    int n = in_sizes[0] / C0; if (n > NN) n = NN;
    int E = in_sizes[1] / 2;  if (E > NE) E = NE;
    int nwarps = (n + NPW - 1) / NPW;
    int nblocks = (nwarps + 7) / 8;
    int npairs = (E + 1) / 2;

    k_init<<<(n + 255) / 256, 256>>>((const unsigned*)ei, n, E);
    k_fill<<<(npairs + 255) / 256, 256>>>(ei, E);
    k_scale0<<<(4 * n + 255) / 256, 256>>>(x, n);
    k_gather1<<<nblocks, 256>>>(n);
    k_mlp<<<(n + 255) / 256, 256>>>(W1, b1, W2, n);
    k_layer2<<<nblocks, 256>>>(out, b2, n);
}